// round 1
// baseline (speedup 1.0000x reference)
#include <cuda_runtime.h>
#include <math.h>

// ---------------------------------------------------------------------------
// SoftLabelLoss: loss = max( (1/B) * sum_i [ e[t_i] - dot(soft[t_i], x_i) + lse(x_i) ], 0 )
//   soft[t][c] = 0.8 * (c==t) + 0.2 * sim[t][c] / rowsum(sim[t])
//   e[t]       = sum_c soft[t][c] * log(soft[t][c])      (0*log0 := 0)
// ---------------------------------------------------------------------------

#define MAXC 256
#define MAXBLOCKS 1024

__device__ float  g_soft[MAXC * MAXC];   // precomputed soft-label table
__device__ float  g_ent[MAXC];           // per-class entropy term
__device__ double g_part[MAXBLOCKS];     // per-block partial sums

// --- prep: build soft table + entropy per class (one block per class) -------
__global__ void slloss_prep(const float* __restrict__ sim, int C) {
    int t = blockIdx.x;
    int c = threadIdx.x;               // blockDim.x == 256 >= C
    __shared__ float s_row[MAXC];
    __shared__ float s_red[256];

    float v = (c < C) ? sim[(size_t)t * C + c] : 0.0f;
    if (c < C) s_row[c] = v;
    s_red[c] = v;
    __syncthreads();
    #pragma unroll
    for (int s = 128; s > 0; s >>= 1) {
        if (c < s) s_red[c] += s_red[c + s];
        __syncthreads();
    }
    float inv = 1.0f / s_red[0];
    __syncthreads();

    float p = 0.0f;
    if (c < C) {
        float soft = 0.2f * s_row[c] * inv + (c == t ? 0.8f : 0.0f);
        g_soft[t * C + c] = soft;
        p = (soft > 0.0f) ? soft * __logf(soft) : 0.0f;
    }
    s_red[c] = p;
    __syncthreads();
    #pragma unroll
    for (int s = 128; s > 0; s >>= 1) {
        if (c < s) s_red[c] += s_red[c + s];
        __syncthreads();
    }
    if (c == 0) g_ent[t] = s_red[0];
}

// --- main: warp-per-row, single pass over logits -----------------------------
__global__ __launch_bounds__(1024, 1)
void slloss_main(const float* __restrict__ logits,
                 const int*   __restrict__ targets,
                 int B, int C) {
    extern __shared__ float s_soft[];    // C*C floats
    const int tid  = threadIdx.x;
    const int nthr = blockDim.x;

    // Stage soft table into shared memory (one-time per block)
    for (int i = tid; i < C * C; i += nthr) s_soft[i] = g_soft[i];
    __syncthreads();

    const int lane = tid & 31;
    const int warp = tid >> 5;
    const int wpb  = nthr >> 5;
    long long gw = (long long)blockIdx.x * wpb + warp;
    long long nw = (long long)gridDim.x  * wpb;

    const int  C2   = C >> 1;
    const bool codd = (C & 1) != 0;

    float acc = 0.0f;   // lane-private: accumulates (-dot partials) and lane0: (e[t] + lse)

    for (long long row = gw; row < B; row += nw) {
        int t = __ldg(&targets[row]);
        if (t < 0) continue;            // IGNORE_INDEX -> contributes 0

        const float2* __restrict__ lg = (const float2*)(logits + (size_t)row * C);
        const float2* __restrict__ sw = (const float2*)(s_soft + t * C);

        float se = 0.0f, dt = 0.0f;
        #pragma unroll 4
        for (int j = lane; j < C2; j += 32) {
            float2 x = lg[j];
            float2 w = sw[j];
            se += __expf(x.x) + __expf(x.y);
            dt = fmaf(w.x, x.x, dt);
            dt = fmaf(w.y, x.y, dt);
        }
        if (codd && lane == 0) {
            float x = logits[(size_t)row * C + C - 1];
            se += __expf(x);
            dt = fmaf(s_soft[t * C + C - 1], x, dt);
        }

        // only lse needs a per-row warp reduce; dot partials stay lane-private
        #pragma unroll
        for (int o = 16; o; o >>= 1) se += __shfl_xor_sync(0xffffffffu, se, o);

        acc -= dt;
        if (lane == 0) acc += __ldg(&g_ent[t]) + __logf(se);
    }

    // final hierarchical reduce in double
    double d = (double)acc;
    #pragma unroll
    for (int o = 16; o; o >>= 1) d += __shfl_xor_sync(0xffffffffu, d, o);

    __shared__ double s_w[32];
    if (lane == 0) s_w[warp] = d;
    __syncthreads();
    if (warp == 0) {
        double v = (lane < wpb) ? s_w[lane] : 0.0;
        #pragma unroll
        for (int o = 16; o; o >>= 1) v += __shfl_xor_sync(0xffffffffu, v, o);
        if (lane == 0) g_part[blockIdx.x] = v;
    }
}

// --- final: sum block partials, scale, clamp ---------------------------------
__global__ void slloss_final(float* __restrict__ out, int nblocks, int B) {
    double s = 0.0;
    for (int i = threadIdx.x; i < nblocks; i += 32) s += g_part[i];
    #pragma unroll
    for (int o = 16; o; o >>= 1) s += __shfl_xor_sync(0xffffffffu, s, o);
    if (threadIdx.x == 0) {
        double loss = s / (double)B;
        out[0] = (float)(loss > 0.0 ? loss : 0.0);
    }
}

extern "C" void kernel_launch(void* const* d_in, const int* in_sizes, int n_in,
                              void* d_out, int out_size) {
    const float* logits  = (const float*)d_in[0];
    const int*   targets = (const int*)  d_in[1];
    const float* sim     = (const float*)d_in[2];
    float*       out     = (float*)d_out;

    int B = in_sizes[1];
    int C = in_sizes[0] / B;

    // precompute soft-label table + entropies
    slloss_prep<<<C, 256>>>(sim, C);

    int nsm = 148;
    cudaDeviceGetAttribute(&nsm, cudaDevAttrMultiProcessorCount, 0);
    if (nsm > MAXBLOCKS) nsm = MAXBLOCKS;

    size_t smem = (size_t)C * C * sizeof(float);
    cudaFuncSetAttribute(slloss_main, cudaFuncAttributeMaxDynamicSharedMemorySize, (int)smem);

    slloss_main<<<nsm, 1024, smem>>>(logits, targets, B, C);
    slloss_final<<<1, 32>>>(out, nsm, B);
}

// round 2
// speedup vs baseline: 2.0236x; 2.0236x over previous
#include <cuda_runtime.h>
#include <math.h>

// ---------------------------------------------------------------------------
// SoftLabelLoss: loss = max( (1/B) * sum_i [ e[t_i] - dot(soft[t_i], x_i) + lse(x_i) ], 0 )
//   soft[t][c] = 0.8*(c==t) + 0.2 * sim[t][c]/rowsum(sim[t])
//   e[t]       = sum_c soft[t][c]*log(soft[t][c])
// Single pass over logits; soft table + entropies precomputed, staged in smem.
// ---------------------------------------------------------------------------

#define MAXC 256
#define MAXBLOCKS 1024

__device__ float  g_soft[MAXC * MAXC];
__device__ float  g_ent[MAXC];
__device__ double g_part[MAXBLOCKS];

// --- prep: build soft table + entropy per class (one block per class) -------
__global__ void slloss_prep(const float* __restrict__ sim, int C) {
    int t = blockIdx.x;
    int c = threadIdx.x;               // blockDim.x == 256 >= C
    __shared__ float s_row[MAXC];
    __shared__ float s_red[256];

    float v = (c < C) ? sim[(size_t)t * C + c] : 0.0f;
    if (c < C) s_row[c] = v;
    s_red[c] = v;
    __syncthreads();
    #pragma unroll
    for (int s = 128; s > 0; s >>= 1) {
        if (c < s) s_red[c] += s_red[c + s];
        __syncthreads();
    }
    float inv = 1.0f / s_red[0];
    __syncthreads();

    float p = 0.0f;
    if (c < C) {
        float soft = 0.2f * s_row[c] * inv + (c == t ? 0.8f : 0.0f);
        g_soft[t * C + c] = soft;
        p = (soft > 0.0f) ? soft * __logf(soft) : 0.0f;
    }
    s_red[c] = p;
    __syncthreads();
    #pragma unroll
    for (int s = 128; s > 0; s >>= 1) {
        if (c < s) s_red[c] += s_red[c + s];
        __syncthreads();
    }
    if (c == 0) g_ent[t] = s_red[0];
}

// --- main (templated on # of float2 chunks per row): warp-per-row,
//     contiguous row chunks, batched targets, 1-row register prefetch --------
template<int NCH>
__global__ __launch_bounds__(1024, 1)
void slloss_main_t(const float* __restrict__ logits,
                   const int*   __restrict__ targets,
                   int B, int C) {
    extern __shared__ float smem[];
    float* s_soft = smem;            // C*C
    float* s_ent  = smem + C * C;    // C

    const int tid = threadIdx.x;
    for (int i = tid; i < C * C; i += 1024) s_soft[i] = g_soft[i];
    if (tid < C) s_ent[tid] = g_ent[tid];
    __syncthreads();

    const int lane = tid & 31;
    const int warp = tid >> 5;
    const int NW   = gridDim.x * 32;
    const int gw   = blockIdx.x * 32 + warp;
    const int C2   = C >> 1;         // C even on this path

    long long per = ((long long)B + NW - 1) / NW;
    long long r0  = (long long)gw * per;
    long long r1  = r0 + per; if (r1 > B) r1 = B;

    float acc = 0.0f;

    for (long long base = r0; base < r1; base += 32) {
        const int nrows = (int)((r1 - base) < 32 ? (r1 - base) : 32);

        // one coalesced target load per 32 rows
        int t32 = (lane < nrows) ? __ldg(targets + base + lane) : 0;

        const float* rp = logits + base * (long long)C;

        float2 cur[NCH], nxt[NCH];
        #pragma unroll
        for (int k = 0; k < NCH; k++) {
            int j = lane + 32 * k;
            cur[k] = (j < C2) ? ((const float2*)rp)[j] : make_float2(0.f, 0.f);
        }

        for (int r = 0; r < nrows; r++) {
            // prefetch next row while computing current
            if (r + 1 < nrows) {
                const float2* np = (const float2*)(rp + (long long)(r + 1) * C);
                #pragma unroll
                for (int k = 0; k < NCH; k++) {
                    int j = lane + 32 * k;
                    nxt[k] = (j < C2) ? np[j] : make_float2(0.f, 0.f);
                }
            }

            int  t     = __shfl_sync(0xffffffffu, t32, r);
            bool valid = (t >= 0);
            int  tw    = valid ? t : 0;
            const float2* sw = (const float2*)(s_soft + tw * C);

            float se = 0.0f, dt = 0.0f;
            #pragma unroll
            for (int k = 0; k < NCH; k++) {
                int j = lane + 32 * k;
                if (j < C2) {
                    float2 x = cur[k];
                    float2 w = sw[j];
                    se += __expf(x.x) + __expf(x.y);
                    dt = fmaf(w.x, x.x, dt);
                    dt = fmaf(w.y, x.y, dt);
                }
            }
            #pragma unroll
            for (int o = 16; o; o >>= 1)
                se += __shfl_xor_sync(0xffffffffu, se, o);

            if (valid) {
                acc -= dt;
                if (lane == 0) acc += s_ent[t] + __logf(se);
            }

            #pragma unroll
            for (int k = 0; k < NCH; k++) cur[k] = nxt[k];
        }
    }

    // hierarchical reduce in double
    double d = (double)acc;
    #pragma unroll
    for (int o = 16; o; o >>= 1) d += __shfl_xor_sync(0xffffffffu, d, o);

    __shared__ double s_w[32];
    if (lane == 0) s_w[warp] = d;
    __syncthreads();
    if (warp == 0) {
        double v = s_w[lane];
        #pragma unroll
        for (int o = 16; o; o >>= 1) v += __shfl_xor_sync(0xffffffffu, v, o);
        if (lane == 0) g_part[blockIdx.x] = v;
    }
}

// --- generic fallback (any C) -----------------------------------------------
__global__ __launch_bounds__(1024, 1)
void slloss_main_gen(const float* __restrict__ logits,
                     const int*   __restrict__ targets,
                     int B, int C) {
    extern __shared__ float smem[];
    float* s_soft = smem;
    float* s_ent  = smem + C * C;
    const int tid = threadIdx.x;
    for (int i = tid; i < C * C; i += 1024) s_soft[i] = g_soft[i];
    if (tid < C) s_ent[tid] = g_ent[tid];
    __syncthreads();

    const int lane = tid & 31, warp = tid >> 5;
    const int NW = gridDim.x * 32;
    const int gw = blockIdx.x * 32 + warp;

    long long per = ((long long)B + NW - 1) / NW;
    long long r0 = (long long)gw * per;
    long long r1 = r0 + per; if (r1 > B) r1 = B;

    float acc = 0.0f;
    for (long long row = r0; row < r1; row++) {
        int t = __ldg(&targets[row]);
        if (t < 0) continue;
        const float* lg = logits + (size_t)row * C;
        const float* sw = s_soft + t * C;
        float se = 0.f, dt = 0.f;
        for (int c = lane; c < C; c += 32) {
            float x = lg[c];
            se += __expf(x);
            dt = fmaf(sw[c], x, dt);
        }
        #pragma unroll
        for (int o = 16; o; o >>= 1) se += __shfl_xor_sync(0xffffffffu, se, o);
        acc -= dt;
        if (lane == 0) acc += s_ent[t] + __logf(se);
    }

    double d = (double)acc;
    #pragma unroll
    for (int o = 16; o; o >>= 1) d += __shfl_xor_sync(0xffffffffu, d, o);
    __shared__ double s_w[32];
    if (lane == 0) s_w[warp] = d;
    __syncthreads();
    if (warp == 0) {
        double v = s_w[lane];
        #pragma unroll
        for (int o = 16; o; o >>= 1) v += __shfl_xor_sync(0xffffffffu, v, o);
        if (lane == 0) g_part[blockIdx.x] = v;
    }
}

// --- final: sum block partials, scale, clamp ---------------------------------
__global__ void slloss_final(float* __restrict__ out, int nblocks, int B) {
    double s = 0.0;
    for (int i = threadIdx.x; i < nblocks; i += 32) s += g_part[i];
    #pragma unroll
    for (int o = 16; o; o >>= 1) s += __shfl_xor_sync(0xffffffffu, s, o);
    if (threadIdx.x == 0) {
        double loss = s / (double)B;
        out[0] = (float)(loss > 0.0 ? loss : 0.0);
    }
}

extern "C" void kernel_launch(void* const* d_in, const int* in_sizes, int n_in,
                              void* d_out, int out_size) {
    const float* logits  = (const float*)d_in[0];
    const int*   targets = (const int*)  d_in[1];
    const float* sim     = (const float*)d_in[2];
    float*       out     = (float*)d_out;

    int B = in_sizes[1];
    int C = in_sizes[0] / B;

    slloss_prep<<<C, 256>>>(sim, C);

    int nsm = 148;
    cudaDeviceGetAttribute(&nsm, cudaDevAttrMultiProcessorCount, 0);
    if (nsm > MAXBLOCKS) nsm = MAXBLOCKS;

    size_t smem = (size_t)(C * C + C) * sizeof(float);

    int nch = ((C >> 1) + 31) / 32;     // float2 chunks per row
    bool even = (C & 1) == 0;

    if (even && nch >= 1 && nch <= 4) {
        switch (nch) {
        case 1:
            cudaFuncSetAttribute(slloss_main_t<1>, cudaFuncAttributeMaxDynamicSharedMemorySize, (int)smem);
            slloss_main_t<1><<<nsm, 1024, smem>>>(logits, targets, B, C); break;
        case 2:
            cudaFuncSetAttribute(slloss_main_t<2>, cudaFuncAttributeMaxDynamicSharedMemorySize, (int)smem);
            slloss_main_t<2><<<nsm, 1024, smem>>>(logits, targets, B, C); break;
        case 3:
            cudaFuncSetAttribute(slloss_main_t<3>, cudaFuncAttributeMaxDynamicSharedMemorySize, (int)smem);
            slloss_main_t<3><<<nsm, 1024, smem>>>(logits, targets, B, C); break;
        case 4:
            cudaFuncSetAttribute(slloss_main_t<4>, cudaFuncAttributeMaxDynamicSharedMemorySize, (int)smem);
            slloss_main_t<4><<<nsm, 1024, smem>>>(logits, targets, B, C); break;
        }
    } else {
        cudaFuncSetAttribute(slloss_main_gen, cudaFuncAttributeMaxDynamicSharedMemorySize, (int)smem);
        slloss_main_gen<<<nsm, 1024, smem>>>(logits, targets, B, C);
    }

    slloss_final<<<1, 32>>>(out, nsm, B);
}